// round 6
// baseline (speedup 1.0000x reference)
#include <cuda_runtime.h>

// SGConv K=3 via CSR gather hops; final GEMM fused into hop 3.
// Fixed shape: N=100000, E=1600000, F_in=32, F_out=64.
// Launch chain (8): prep, count, scan1(+dinv), scan2, fill, gather, gather,
//                   gather+gemm.

#define NN 100000
#define EE 1600000
#define F_IN 32
#define F_OUT 64
#define SCAN_B 512
#define NBLK ((NN + SCAN_B - 1) / SCAN_B)

// ---- device scratch ----
__device__ __align__(16) int   g_degi    [NN];   // in-degree (excl. self-loop)
__device__ __align__(16) int   g_rowstart[NN];   // block-local exclusive scan
__device__ __align__(16) int   g_cursor  [NN];
__device__ __align__(16) int   g_blksum  [NBLK];
__device__ __align__(16) int   g_blkoff  [NBLK];
__device__ __align__(16) float g_dinv    [NN];
__device__ __align__(16) int   g_src     [EE];
__device__ __align__(16) int   g_dst     [EE];
__device__ __align__(16) int2  g_csr     [EE];   // .x = src node, .y = norm bits
__device__ __align__(16) float g_hA      [(size_t)NN * F_IN];
__device__ __align__(16) float g_hB      [(size_t)NN * F_IN];
__device__ int g_is64;

__device__ __forceinline__ float* buf_sel(int which) {
    return which == 0 ? g_hA : g_hB;
}

// zero counters; thread (0,0) sniffs edge-index dtype (int64 values all < NN;
// fused int32 pairs read as int64 are >= 2^32 with overwhelming probability).
__global__ void k_prep(const void* ei) {
    int i = blockIdx.x * blockDim.x + threadIdx.x;
    if (i < NN) { g_degi[i] = 0; g_cursor[i] = 0; }
    if (i == 0) {
        const long long* e64 = (const long long*)ei;
        int ok = 1;
        for (int j = 0; j < 64; j++) {
            long long v = e64[j];
            if (v < 0 || v >= NN) { ok = 0; break; }
        }
        g_is64 = ok;
    }
}

// per edge: decode indices, stash int32 copies, count in-degree at dst
__global__ void k_count(const void* __restrict__ ei) {
    int e = blockIdx.x * blockDim.x + threadIdx.x;
    if (e >= EE) return;
    int s, d;
    if (g_is64) {
        const long long* e64 = (const long long*)ei;
        s = (int)e64[e];
        d = (int)e64[(size_t)EE + e];
    } else {
        const int* e32 = (const int*)ei;
        s = e32[e];
        d = e32[EE + e];
    }
    if ((unsigned)s >= NN) s = 0;
    if ((unsigned)d >= NN) d = 0;
    g_src[e] = s;
    g_dst[e] = d;
    atomicAdd(&g_degi[d], 1);
}

// block-level exclusive scan of degi -> rowstart (block-local) + block sums;
// also computes dinv = rsqrt(deg+1).
__global__ void k_scan1() {
    __shared__ int sh[SCAN_B];
    int tid = threadIdx.x;
    int i = blockIdx.x * SCAN_B + tid;
    int v = (i < NN) ? g_degi[i] : 0;
    if (i < NN) g_dinv[i] = rsqrtf((float)(v + 1));
    sh[tid] = v;
    __syncthreads();
#pragma unroll
    for (int off = 1; off < SCAN_B; off <<= 1) {
        int t = (tid >= off) ? sh[tid - off] : 0;
        __syncthreads();
        sh[tid] += t;
        __syncthreads();
    }
    if (i < NN) g_rowstart[i] = sh[tid] - v;  // exclusive, block-local
    if (tid == SCAN_B - 1) g_blksum[blockIdx.x] = sh[tid];
}

// scan the 196 block sums (single thread; tiny)
__global__ void k_scan2() {
    int run = 0;
    for (int b = 0; b < NBLK; b++) { g_blkoff[b] = run; run += g_blksum[b]; }
}

// per edge: place (src, norm) into dst's CSR slot (global offset resolved here)
__global__ void k_fill() {
    int e = blockIdx.x * blockDim.x + threadIdx.x;
    if (e >= EE) return;
    int s = g_src[e];
    int d = g_dst[e];
    int pos = g_rowstart[d] + g_blkoff[d >> 9] + atomicAdd(&g_cursor[d], 1);
    g_csr[pos] = make_int2(s, __float_as_int(g_dinv[s] * g_dinv[d]));
}

// gather hop: one warp per node, lane = feature column, 8 nodes per block.
// If final != 0, fuse the linear layer: out[node,:] = h[node,:] @ W^T + b.
__global__ void __launch_bounds__(256) k_gather(
    const float* __restrict__ x_ext, int src_sel, int dst_sel, int final_,
    const float* __restrict__ W, const float* __restrict__ b,
    float* __restrict__ out)
{
    __shared__ float shh[8][F_IN];          // per-warp h row (final only)
    __shared__ float sWT[F_IN * F_OUT];     // W transposed: [c][o]
    __shared__ float sb [F_OUT];

    int tid  = threadIdx.x;
    int wid  = tid >> 5;
    int lane = tid & 31;
    int node = blockIdx.x * 8 + wid;        // NN % 8 == 0 -> always valid

    if (final_) {
        for (int i = tid; i < F_IN * F_OUT; i += 256) {
            int o = i >> 5, c = i & 31;
            sWT[c * F_OUT + o] = W[i];
        }
        if (tid < F_OUT) sb[tid] = b[tid];
    }

    const float* __restrict__ hold = (src_sel < 0) ? x_ext : buf_sel(src_sel);

    float di  = g_dinv[node];
    float acc = di * di * hold[(size_t)node * F_IN + lane];   // self-loop

    int beg = g_rowstart[node] + g_blkoff[node >> 9];
    int end = beg + g_degi[node];
    const int2* __restrict__ csr = g_csr;

    int e = beg;
    for (; e + 8 <= end; e += 8) {
        int2 c0 = csr[e + 0], c1 = csr[e + 1], c2 = csr[e + 2], c3 = csr[e + 3];
        int2 c4 = csr[e + 4], c5 = csr[e + 5], c6 = csr[e + 6], c7 = csr[e + 7];
        float v0 = hold[(size_t)c0.x * F_IN + lane];
        float v1 = hold[(size_t)c1.x * F_IN + lane];
        float v2 = hold[(size_t)c2.x * F_IN + lane];
        float v3 = hold[(size_t)c3.x * F_IN + lane];
        float v4 = hold[(size_t)c4.x * F_IN + lane];
        float v5 = hold[(size_t)c5.x * F_IN + lane];
        float v6 = hold[(size_t)c6.x * F_IN + lane];
        float v7 = hold[(size_t)c7.x * F_IN + lane];
        acc += __int_as_float(c0.y) * v0;
        acc += __int_as_float(c1.y) * v1;
        acc += __int_as_float(c2.y) * v2;
        acc += __int_as_float(c3.y) * v3;
        acc += __int_as_float(c4.y) * v4;
        acc += __int_as_float(c5.y) * v5;
        acc += __int_as_float(c6.y) * v6;
        acc += __int_as_float(c7.y) * v7;
    }
    for (; e < end; e++) {
        int2 ce = csr[e];
        acc += __int_as_float(ce.y) * hold[(size_t)ce.x * F_IN + lane];
    }

    if (!final_) {
        float* __restrict__ hnew = buf_sel(dst_sel);
        hnew[(size_t)node * F_IN + lane] = acc;
        return;
    }

    // fused linear: warp holds h[node, lane] in acc
    shh[wid][lane] = acc;
    __syncthreads();

    float a0 = sb[lane];
    float a1 = sb[lane + 32];
#pragma unroll
    for (int c = 0; c < F_IN; c++) {
        float h = shh[wid][c];                 // broadcast
        a0 += h * sWT[c * F_OUT + lane];       // conflict-free
        a1 += h * sWT[c * F_OUT + lane + 32];
    }
    out[(size_t)node * F_OUT + lane]      = a0;
    out[(size_t)node * F_OUT + lane + 32] = a1;
}

static inline int cdiv(int a, int b) { return (a + b - 1) / b; }

extern "C" void kernel_launch(void* const* d_in, const int* in_sizes, int n_in,
                              void* d_out, int out_size) {
    const float* x  = (const float*)d_in[0];
    const void*  ei = (const void*)d_in[1];
    const float* W  = (const float*)d_in[2];
    const float* b  = (const float*)d_in[3];
    float* out = (float*)d_out;

    const int T = 256;

    // CSR build + normalization (5 launches)
    k_prep <<<cdiv(NN, T), T>>>(ei);
    k_count<<<cdiv(EE, T), T>>>(ei);
    k_scan1<<<NBLK, SCAN_B>>>();
    k_scan2<<<1, 1>>>();
    k_fill <<<cdiv(EE, T), T>>>();

    // 3 gather hops (8 nodes / 256-thread block); hop 3 fuses the GEMM
    int gblocks = NN / 8;  // 12500
    k_gather<<<gblocks, T>>>(x, -1, 0, 0, W, b, out);  // x  -> hA
    k_gather<<<gblocks, T>>>(x,  0, 1, 0, W, b, out);  // hA -> hB
    k_gather<<<gblocks, T>>>(x,  1, 0, 1, W, b, out);  // hB -> (fused GEMM) out
}

// round 8
// speedup vs baseline: 1.5845x; 1.5845x over previous
#include <cuda_runtime.h>

// SGConv K=3 via CSR gather (pull) hops: h = A_hat^3 x ; out = h @ W^T + b
// Fixed shape: N=100000, E=1600000, F_in=32, F_out=64.
// R6 = R4 hot kernels (k_gather / k_gemm byte-identical) + trimmed prep chain:
//   detect fused into zero, dinv fused into scan1, scan2 parallelized.

#define NN 100000
#define EE 1600000
#define F_IN 32
#define F_OUT 64
#define SCAN_B 512
#define NBLK ((NN + SCAN_B - 1) / SCAN_B)

// ---- device scratch ----
__device__ __align__(16) int   g_degi    [NN];     // in-degree (excl. self-loop)
__device__ __align__(16) int   g_rowstart[NN];     // CSR row offsets (exclusive scan)
__device__ __align__(16) int   g_cursor  [NN];     // fill cursors
__device__ __align__(16) int   g_blksum  [NBLK];
__device__ __align__(16) int   g_blkoff  [NBLK];
__device__ __align__(16) float g_dinv    [NN];
__device__ __align__(16) int   g_src     [EE];
__device__ __align__(16) int   g_dst     [EE];
__device__ __align__(16) int   g_csr_src [EE];
__device__ __align__(16) float g_csr_norm[EE];
__device__ __align__(16) float g_hA      [(size_t)NN * F_IN];
__device__ __align__(16) float g_hB      [(size_t)NN * F_IN];
__device__ int g_is64;

__device__ __forceinline__ float* buf_sel(int which) {
    return which == 0 ? g_hA : g_hB;
}

// zero counters; thread 0 sniffs edge-index dtype (int64 values all < NN;
// fused int32 pairs read as int64 are >= 2^32 with overwhelming probability).
__global__ void k_zero(const void* ei) {
    int i = blockIdx.x * blockDim.x + threadIdx.x;
    if (i < NN) { g_degi[i] = 0; g_cursor[i] = 0; }
    if (i == 0) {
        const long long* e64 = (const long long*)ei;
        int ok = 1;
        for (int j = 0; j < 64; j++) {
            long long v = e64[j];
            if (v < 0 || v >= NN) { ok = 0; break; }
        }
        g_is64 = ok;
    }
}

// per edge: read index (either dtype), store int32 copies, count in-degree
__global__ void k_count(const void* __restrict__ ei) {
    int e = blockIdx.x * blockDim.x + threadIdx.x;
    if (e >= EE) return;
    int s, d;
    if (g_is64) {
        const long long* e64 = (const long long*)ei;
        s = (int)e64[e];
        d = (int)e64[(size_t)EE + e];
    } else {
        const int* e32 = (const int*)ei;
        s = e32[e];
        d = e32[EE + e];
    }
    if ((unsigned)s >= NN) s = 0;
    if ((unsigned)d >= NN) d = 0;
    g_src[e] = s;
    g_dst[e] = d;
    atomicAdd(&g_degi[d], 1);
}

// block-level scan of g_degi -> exclusive offsets + block sums; also dinv.
__global__ void k_scan1() {
    __shared__ int sh[SCAN_B];
    int tid = threadIdx.x;
    int i = blockIdx.x * SCAN_B + tid;
    int v = (i < NN) ? g_degi[i] : 0;
    if (i < NN) g_dinv[i] = rsqrtf((float)(v + 1));  // +1 self-loop, always > 0
    sh[tid] = v;
    __syncthreads();
#pragma unroll
    for (int off = 1; off < SCAN_B; off <<= 1) {
        int t = (tid >= off) ? sh[tid - off] : 0;
        __syncthreads();
        sh[tid] += t;
        __syncthreads();
    }
    if (i < NN) g_rowstart[i] = sh[tid] - v;  // exclusive
    if (tid == SCAN_B - 1) g_blksum[blockIdx.x] = sh[tid];
}

// parallel scan of the NBLK (=196) block sums: one 256-thread block.
__global__ void k_scan2() {
    __shared__ int sh[256];
    int tid = threadIdx.x;
    int v = (tid < NBLK) ? g_blksum[tid] : 0;
    sh[tid] = v;
    __syncthreads();
#pragma unroll
    for (int off = 1; off < 256; off <<= 1) {
        int t = (tid >= off) ? sh[tid - off] : 0;
        __syncthreads();
        sh[tid] += t;
        __syncthreads();
    }
    if (tid < NBLK) g_blkoff[tid] = sh[tid] - v;  // exclusive
}

__global__ void k_scan3() {
    int i = blockIdx.x * blockDim.x + threadIdx.x;
    if (i < NN) g_rowstart[i] += g_blkoff[i / SCAN_B];
}

// per edge: place (src, norm) into the dst's CSR slot
__global__ void k_fill() {
    int e = blockIdx.x * blockDim.x + threadIdx.x;
    if (e >= EE) return;
    int s = g_src[e];
    int d = g_dst[e];
    int pos = g_rowstart[d] + atomicAdd(&g_cursor[d], 1);
    g_csr_src[pos]  = s;
    g_csr_norm[pos] = g_dinv[s] * g_dinv[d];
}

// gather hop: one warp per node, lane = feature column. No atomics.
// (byte-identical to the 183.6us R4 version)
__global__ void k_gather(const float* __restrict__ x_ext, int src_sel, int dst_sel) {
    int t = blockIdx.x * blockDim.x + threadIdx.x;
    int node = t >> 5;
    int lane = t & 31;
    if (node >= NN) return;
    const float* __restrict__ hold = (src_sel < 0) ? x_ext : buf_sel(src_sel);
    float* __restrict__ hnew = buf_sel(dst_sel);

    float di = g_dinv[node];
    float acc = di * di * hold[(size_t)node * F_IN + lane];  // self-loop term

    int beg = g_rowstart[node];
    int end = beg + g_degi[node];
    int e = beg;
    // 4-way unroll for memory-level parallelism on the L2 gathers
    for (; e + 3 < end; e += 4) {
        int   s0 = g_csr_src[e + 0], s1 = g_csr_src[e + 1];
        int   s2 = g_csr_src[e + 2], s3 = g_csr_src[e + 3];
        float n0 = g_csr_norm[e + 0], n1 = g_csr_norm[e + 1];
        float n2 = g_csr_norm[e + 2], n3 = g_csr_norm[e + 3];
        float v0 = hold[(size_t)s0 * F_IN + lane];
        float v1 = hold[(size_t)s1 * F_IN + lane];
        float v2 = hold[(size_t)s2 * F_IN + lane];
        float v3 = hold[(size_t)s3 * F_IN + lane];
        acc += n0 * v0;
        acc += n1 * v1;
        acc += n2 * v2;
        acc += n3 * v3;
    }
    for (; e < end; e++) {
        acc += g_csr_norm[e] * hold[(size_t)g_csr_src[e] * F_IN + lane];
    }
    hnew[(size_t)node * F_IN + lane] = acc;
}

// out[i,:] = h[i,:] @ W^T + b   (W is [F_OUT, F_IN] row-major). h = g_hA.
__global__ void k_gemm(const float* __restrict__ W,
                       const float* __restrict__ b, float* __restrict__ out) {
    __shared__ float sW[F_OUT * F_IN];
    __shared__ float sb[F_OUT];
    for (int i = threadIdx.x; i < F_OUT * F_IN; i += blockDim.x) sW[i] = W[i];
    if (threadIdx.x < F_OUT) sb[threadIdx.x] = b[threadIdx.x];
    __syncthreads();

    int i = blockIdx.x * blockDim.x + threadIdx.x;
    if (i >= NN) return;

    float4 hr[F_IN / 4];
    const float4* hp = reinterpret_cast<const float4*>(g_hA + (size_t)i * F_IN);
#pragma unroll
    for (int c = 0; c < F_IN / 4; c++) hr[c] = hp[c];

    const float4* sW4 = reinterpret_cast<const float4*>(sW);
    float4* op = reinterpret_cast<float4*>(out + (size_t)i * F_OUT);
#pragma unroll
    for (int og = 0; og < F_OUT / 4; og++) {
        float4 acc = make_float4(sb[4 * og + 0], sb[4 * og + 1], sb[4 * og + 2], sb[4 * og + 3]);
#pragma unroll
        for (int fc = 0; fc < F_IN / 4; fc++) {
            float4 hv = hr[fc];
            float4 w0 = sW4[(4 * og + 0) * (F_IN / 4) + fc];
            float4 w1 = sW4[(4 * og + 1) * (F_IN / 4) + fc];
            float4 w2 = sW4[(4 * og + 2) * (F_IN / 4) + fc];
            float4 w3 = sW4[(4 * og + 3) * (F_IN / 4) + fc];
            acc.x += hv.x * w0.x + hv.y * w0.y + hv.z * w0.z + hv.w * w0.w;
            acc.y += hv.x * w1.x + hv.y * w1.y + hv.z * w1.z + hv.w * w1.w;
            acc.z += hv.x * w2.x + hv.y * w2.y + hv.z * w2.z + hv.w * w2.w;
            acc.w += hv.x * w3.x + hv.y * w3.y + hv.z * w3.z + hv.w * w3.w;
        }
        op[og] = acc;
    }
}

static inline int cdiv(int a, int b) { return (a + b - 1) / b; }

extern "C" void kernel_launch(void* const* d_in, const int* in_sizes, int n_in,
                              void* d_out, int out_size) {
    const float* x  = (const float*)d_in[0];
    const void*  ei = (const void*)d_in[1];
    const float* W  = (const float*)d_in[2];
    const float* b  = (const float*)d_in[3];
    float* out = (float*)d_out;

    const int T = 256;

    // CSR build + normalization (6 launches)
    k_zero <<<cdiv(NN, T), T>>>(ei);
    k_count<<<cdiv(EE, T), T>>>(ei);
    k_scan1<<<NBLK, SCAN_B>>>();
    k_scan2<<<1, 256>>>();
    k_scan3<<<cdiv(NN, T), T>>>();
    k_fill <<<cdiv(EE, T), T>>>();

    // 3 gather hops (warp per node)
    int gthreads = NN * 32;
    k_gather<<<cdiv(gthreads, T), T>>>(x, -1, 0);  // x  -> hA
    k_gather<<<cdiv(gthreads, T), T>>>(x,  0, 1);  // hA -> hB
    k_gather<<<cdiv(gthreads, T), T>>>(x,  1, 0);  // hB -> hA

    // final linear
    k_gemm<<<cdiv(NN, 128), 128>>>(W, b, out);
}

// round 9
// speedup vs baseline: 2.3544x; 1.4859x over previous
#include <cuda_runtime.h>

// SGConv K=3 via CSR gather hops with warp-cooperative index staging.
// Fixed shape: N=100000, E=1600000, F_in=32, F_out=64.
// Hop model: per edge only ~1.03 LDGs (1 coalesced idx load per 32 edges via
// shuffle broadcast + 1 x 128B feature gather) -> LDG-issue floor ~14us/hop,
// LTS floor ~18us/hop.

#define NN 100000
#define EE 1600000
#define F_IN 32
#define F_OUT 64
#define SCAN_B 512
#define NBLK ((NN + SCAN_B - 1) / SCAN_B)

// ---- device scratch ----
__device__ __align__(16) int   g_degi    [NN];     // in-degree (excl. self-loop)
__device__ __align__(16) int   g_rowstart[NN];     // CSR row offsets (exclusive)
__device__ __align__(16) int   g_cursor  [NN];     // fill cursors
__device__ __align__(16) int   g_blksum  [NBLK];
__device__ __align__(16) int   g_blkoff  [NBLK];
__device__ __align__(16) float g_dinv    [NN];
__device__ __align__(16) int   g_src     [EE];
__device__ __align__(16) int   g_dst     [EE];
__device__ __align__(16) int2  g_csr     [EE];     // .x = src, .y = norm bits
__device__ __align__(16) float g_hA      [(size_t)NN * F_IN];
__device__ __align__(16) float g_hB      [(size_t)NN * F_IN];
__device__ int g_is64;

__device__ __forceinline__ float* buf_sel(int which) {
    return which == 0 ? g_hA : g_hB;
}

// zero counters; warp 0 of block 0 sniffs edge-index dtype in parallel
// (int64 values are all < NN; int32 pairs read as int64 are >= 2^32 w.h.p.).
__global__ void k_zero(const void* ei) {
    int i = blockIdx.x * blockDim.x + threadIdx.x;
    if (i < NN) { g_degi[i] = 0; g_cursor[i] = 0; }
    if (blockIdx.x == 0 && threadIdx.x < 32) {
        const long long* e64 = (const long long*)ei;
        long long v0 = e64[threadIdx.x];
        long long v1 = e64[32 + threadIdx.x];
        int ok = (v0 >= 0 && v0 < NN && v1 >= 0 && v1 < NN);
        int all = __all_sync(0xFFFFFFFFu, ok);
        if (threadIdx.x == 0) g_is64 = all;
    }
}

// per edge: decode indices (either dtype), stash int32 copies, count in-degree
__global__ void k_count(const void* __restrict__ ei) {
    int e = blockIdx.x * blockDim.x + threadIdx.x;
    if (e >= EE) return;
    int s, d;
    if (g_is64) {
        const long long* e64 = (const long long*)ei;
        s = (int)e64[e];
        d = (int)e64[(size_t)EE + e];
    } else {
        const int* e32 = (const int*)ei;
        s = e32[e];
        d = e32[EE + e];
    }
    if ((unsigned)s >= NN) s = 0;
    if ((unsigned)d >= NN) d = 0;
    g_src[e] = s;
    g_dst[e] = d;
    atomicAdd(&g_degi[d], 1);
}

// block-level scan of g_degi -> exclusive offsets + block sums; also dinv.
__global__ void k_scan1() {
    __shared__ int sh[SCAN_B];
    int tid = threadIdx.x;
    int i = blockIdx.x * SCAN_B + tid;
    int v = (i < NN) ? g_degi[i] : 0;
    if (i < NN) g_dinv[i] = rsqrtf((float)(v + 1));  // +1 self-loop, > 0
    sh[tid] = v;
    __syncthreads();
#pragma unroll
    for (int off = 1; off < SCAN_B; off <<= 1) {
        int t = (tid >= off) ? sh[tid - off] : 0;
        __syncthreads();
        sh[tid] += t;
        __syncthreads();
    }
    if (i < NN) g_rowstart[i] = sh[tid] - v;  // exclusive, block-local
    if (tid == SCAN_B - 1) g_blksum[blockIdx.x] = sh[tid];
}

// parallel scan of the NBLK (=196) block sums: one 256-thread block.
__global__ void k_scan2() {
    __shared__ int sh[256];
    int tid = threadIdx.x;
    int v = (tid < NBLK) ? g_blksum[tid] : 0;
    sh[tid] = v;
    __syncthreads();
#pragma unroll
    for (int off = 1; off < 256; off <<= 1) {
        int t = (tid >= off) ? sh[tid - off] : 0;
        __syncthreads();
        sh[tid] += t;
        __syncthreads();
    }
    if (tid < NBLK) g_blkoff[tid] = sh[tid] - v;  // exclusive
}

__global__ void k_scan3() {
    int i = blockIdx.x * blockDim.x + threadIdx.x;
    if (i < NN) g_rowstart[i] += g_blkoff[i / SCAN_B];
}

// per edge: place (src, norm) packed int2 into the dst's CSR slot
__global__ void k_fill() {
    int e = blockIdx.x * blockDim.x + threadIdx.x;
    if (e >= EE) return;
    int s = g_src[e];
    int d = g_dst[e];
    int pos = g_rowstart[d] + atomicAdd(&g_cursor[d], 1);
    g_csr[pos] = make_int2(s, __float_as_int(g_dinv[s] * g_dinv[d]));
}

// gather hop: one warp per node, lane = feature column.
// Warp-cooperatively stages 32 CSR entries with ONE coalesced LDG, then
// shuffle-broadcasts each edge; 4 independent gathers in flight per batch.
__global__ void k_gather(const float* __restrict__ x_ext, int src_sel, int dst_sel) {
    int t = blockIdx.x * blockDim.x + threadIdx.x;
    int node = t >> 5;
    int lane = t & 31;
    if (node >= NN) return;
    const float* __restrict__ hold = (src_sel < 0) ? x_ext : buf_sel(src_sel);
    float* __restrict__ hnew = buf_sel(dst_sel);

    float di  = g_dinv[node];
    float acc = di * di * hold[(size_t)node * F_IN + lane];  // self-loop term

    int beg = g_rowstart[node];
    int deg = g_degi[node];
    const int2* __restrict__ csr = g_csr;

    for (int base = 0; base < deg; base += 32) {
        int idx = beg + base + lane;
        int last = beg + deg - 1;                 // deg >= 1 inside this loop
        int2 my = csr[idx <= last ? idx : last];  // clamped coalesced load
        int m = deg - base; if (m > 32) m = 32;

        int j = 0;
        for (; j + 4 <= m; j += 4) {
            int   s0 = __shfl_sync(0xFFFFFFFFu, my.x, j + 0);
            int   s1 = __shfl_sync(0xFFFFFFFFu, my.x, j + 1);
            int   s2 = __shfl_sync(0xFFFFFFFFu, my.x, j + 2);
            int   s3 = __shfl_sync(0xFFFFFFFFu, my.x, j + 3);
            float n0 = __int_as_float(__shfl_sync(0xFFFFFFFFu, my.y, j + 0));
            float n1 = __int_as_float(__shfl_sync(0xFFFFFFFFu, my.y, j + 1));
            float n2 = __int_as_float(__shfl_sync(0xFFFFFFFFu, my.y, j + 2));
            float n3 = __int_as_float(__shfl_sync(0xFFFFFFFFu, my.y, j + 3));
            float v0 = hold[(size_t)s0 * F_IN + lane];
            float v1 = hold[(size_t)s1 * F_IN + lane];
            float v2 = hold[(size_t)s2 * F_IN + lane];
            float v3 = hold[(size_t)s3 * F_IN + lane];
            acc += n0 * v0;
            acc += n1 * v1;
            acc += n2 * v2;
            acc += n3 * v3;
        }
        for (; j < m; j++) {
            int   s = __shfl_sync(0xFFFFFFFFu, my.x, j);
            float n = __int_as_float(__shfl_sync(0xFFFFFFFFu, my.y, j));
            acc += n * hold[(size_t)s * F_IN + lane];
        }
    }
    hnew[(size_t)node * F_IN + lane] = acc;
}

// out[i,:] = h[i,:] @ W^T + b   (W is [F_OUT, F_IN] row-major). h = g_hA.
__global__ void k_gemm(const float* __restrict__ W,
                       const float* __restrict__ b, float* __restrict__ out) {
    __shared__ float sW[F_OUT * F_IN];
    __shared__ float sb[F_OUT];
    for (int i = threadIdx.x; i < F_OUT * F_IN; i += blockDim.x) sW[i] = W[i];
    if (threadIdx.x < F_OUT) sb[threadIdx.x] = b[threadIdx.x];
    __syncthreads();

    int i = blockIdx.x * blockDim.x + threadIdx.x;
    if (i >= NN) return;

    float4 hr[F_IN / 4];
    const float4* hp = reinterpret_cast<const float4*>(g_hA + (size_t)i * F_IN);
#pragma unroll
    for (int c = 0; c < F_IN / 4; c++) hr[c] = hp[c];

    const float4* sW4 = reinterpret_cast<const float4*>(sW);
    float4* op = reinterpret_cast<float4*>(out + (size_t)i * F_OUT);
#pragma unroll
    for (int og = 0; og < F_OUT / 4; og++) {
        float4 acc = make_float4(sb[4 * og + 0], sb[4 * og + 1], sb[4 * og + 2], sb[4 * og + 3]);
#pragma unroll
        for (int fc = 0; fc < F_IN / 4; fc++) {
            float4 hv = hr[fc];
            float4 w0 = sW4[(4 * og + 0) * (F_IN / 4) + fc];
            float4 w1 = sW4[(4 * og + 1) * (F_IN / 4) + fc];
            float4 w2 = sW4[(4 * og + 2) * (F_IN / 4) + fc];
            float4 w3 = sW4[(4 * og + 3) * (F_IN / 4) + fc];
            acc.x += hv.x * w0.x + hv.y * w0.y + hv.z * w0.z + hv.w * w0.w;
            acc.y += hv.x * w1.x + hv.y * w1.y + hv.z * w1.z + hv.w * w1.w;
            acc.z += hv.x * w2.x + hv.y * w2.y + hv.z * w2.z + hv.w * w2.w;
            acc.w += hv.x * w3.x + hv.y * w3.y + hv.z * w3.z + hv.w * w3.w;
        }
        op[og] = acc;
    }
}

static inline int cdiv(int a, int b) { return (a + b - 1) / b; }

extern "C" void kernel_launch(void* const* d_in, const int* in_sizes, int n_in,
                              void* d_out, int out_size) {
    const float* x  = (const float*)d_in[0];
    const void*  ei = (const void*)d_in[1];
    const float* W  = (const float*)d_in[2];
    const float* b  = (const float*)d_in[3];
    float* out = (float*)d_out;

    const int T = 256;

    // CSR build + normalization
    k_zero <<<cdiv(NN, T), T>>>(ei);
    k_count<<<cdiv(EE, T), T>>>(ei);
    k_scan1<<<NBLK, SCAN_B>>>();
    k_scan2<<<1, 256>>>();
    k_scan3<<<cdiv(NN, T), T>>>();
    k_fill <<<cdiv(EE, T), T>>>();

    // 3 gather hops (warp per node)
    int gthreads = NN * 32;
    k_gather<<<cdiv(gthreads, T), T>>>(x, -1, 0);  // x  -> hA
    k_gather<<<cdiv(gthreads, T), T>>>(x,  0, 1);  // hA -> hB
    k_gather<<<cdiv(gthreads, T), T>>>(x,  1, 0);  // hB -> hA

    // final linear
    k_gemm<<<cdiv(NN, 128), 128>>>(W, b, out);
}